// round 1
// baseline (speedup 1.0000x reference)
#include <cuda_runtime.h>

// sLSTM: T=512 serial steps, B=16, HID=1024, H=4 heads (D=256), G=4 gates.
// Persistent kernel: 128 CTAs (one per (head, 8-channel block)), weights in SMEM,
// f32x2 packed FMA inner loop, one global atomic barrier per step, h double-buffered
// in __device__ global memory (L1-bypassed via ldcg/stcg).

#define T_STEPS 512
#define BATCH   16
#define HID     1024
#define NCTA    128
#define TPB     256
#define WSTRIDE 260   // 256 + 4 pad floats -> rows land on distinct bank groups
#define HSTRIDE 260

__device__ float g_h[2][BATCH][HID];
__device__ unsigned int g_bar_count;
__device__ unsigned int g_bar_gen;

__global__ void prep_kernel() {
    int i = blockIdx.x * blockDim.x + threadIdx.x;
    if (i == 0) { g_bar_count = 0u; g_bar_gen = 0u; }
    float* p = &g_h[0][0][0];
    const int n = 2 * BATCH * HID;
    for (int k = i; k < n; k += gridDim.x * blockDim.x) p[k] = 0.0f;
}

__device__ __forceinline__ void ffma2(unsigned long long &acc,
                                      unsigned long long a,
                                      unsigned long long b) {
    asm("fma.rn.f32x2 %0, %1, %2, %0;" : "+l"(acc) : "l"(a), "l"(b));
}
__device__ __forceinline__ float fold2(unsigned long long a) {
    return __uint_as_float((unsigned)(a & 0xffffffffu)) +
           __uint_as_float((unsigned)(a >> 32));
}
__device__ __forceinline__ float logsigf(float v) {
    // log(sigmoid(v)) = min(v,0) - log1p(exp(-|v|))
    float l = log1pf(expf(-fabsf(v)));
    return (v < 0.0f ? v : 0.0f) - l;
}

__global__ __launch_bounds__(TPB, 1) void slstm_kernel(
    const float* __restrict__ x,     // (512, 16, 4096)
    const float* __restrict__ rk,    // (4, 256, 4, 256)
    const float* __restrict__ bias,  // (4, 4, 256) -> flat 4096
    float* __restrict__ out)         // outs (512,16,1024) ++ final (4,16,1024)
{
    extern __shared__ float smem[];
    float* sW   = smem;                   // 32 * WSTRIDE
    float* sH   = sW + 32 * WSTRIDE;      // 16 * HSTRIDE
    float* sRaw = sH + 16 * HSTRIDE;      // 32 * 16

    const int c     = blockIdx.x;
    const int head  = c >> 5;        // 4 heads
    const int db    = c & 31;        // 32 dd-blocks of 8 channels
    const int dd0   = db << 3;
    const int hbase = head << 8;
    const int tid   = threadIdx.x;

    // GEMM role: thread -> (gate-row r in [0,32), batches b0 and b0+8)
    const int r  = tid >> 3;
    const int b0 = tid & 7;
    const int b1 = b0 + 8;
    const int g2 = r >> 3;
    const int dd = dd0 + (r & 7);
    const int p  = (g2 << 10) + hbase + dd;   // raw channel index in [0,4096)
    const float biasv = bias[p];

    // One-time weight gather into SMEM:
    // W[p][d] = rk[head, (d%64)*4+g2, dd/64, (dd%64)*4 + d/64]
    for (int idx = tid; idx < 32 * 256; idx += TPB) {
        int rr  = idx >> 8, d = idx & 255;
        int gg  = rr >> 3;
        int ddq = dd0 + (rr & 7);
        int a   = ((d & 63) << 2) + gg;
        int gax = ddq >> 6;
        int bb  = ((ddq & 63) << 2) + (d >> 6);
        sW[rr * WSTRIDE + d] = rk[((hbase + a) * 4 + gax) * 256 + bb];
    }

    // Elementwise role: thread u<128 owns state (channel ddl_u, batch b_u)
    const int ddl_u = tid >> 4;
    const int b_u   = tid & 15;
    const int q_u   = hbase + dd0 + ddl_u;
    float st_h = 0.f, st_c = 0.f, st_n = 0.f, st_m = 0.f;

    __syncthreads();

    for (int t = 0; t < T_STEPS; ++t) {
        const int buf = t & 1;
        // Stage this head's h (16 x 256 fp32) from global (L2-coherent path)
        for (int i = tid; i < 1024; i += TPB) {
            int b  = i >> 6;
            int d4 = (i & 63) << 2;
            float4 v = __ldcg((const float4*)&g_h[buf][b][hbase + d4]);
            *(float4*)&sH[b * HSTRIDE + d4] = v;
        }
        float xv0 = __ldg(&x[(t * BATCH + b0) * 4096 + p]);
        float xv1 = __ldg(&x[(t * BATCH + b1) * 4096 + p]);
        __syncthreads();

        // Packed fp32x2 dot over d (pairs over d; fold halves at the end)
        const ulonglong2* wq  = (const ulonglong2*)(sW + r  * WSTRIDE);
        const ulonglong2* h0q = (const ulonglong2*)(sH + b0 * HSTRIDE);
        const ulonglong2* h1q = (const ulonglong2*)(sH + b1 * HSTRIDE);
        unsigned long long a0 = 0ull, a1 = 0ull, a2 = 0ull, a3 = 0ull;
        #pragma unroll 16
        for (int j = 0; j < 64; ++j) {
            ulonglong2 wv  = wq[j];
            ulonglong2 hv0 = h0q[j];
            ulonglong2 hv1 = h1q[j];
            ffma2(a0, wv.x, hv0.x);
            ffma2(a1, wv.x, hv1.x);
            ffma2(a2, wv.y, hv0.y);
            ffma2(a3, wv.y, hv1.y);
        }
        sRaw[r * 16 + b0] = fold2(a0) + fold2(a2) + xv0 + biasv;
        sRaw[r * 16 + b1] = fold2(a1) + fold2(a3) + xv1 + biasv;
        __syncthreads();

        if (tid < 128) {
            float iraw = sRaw[(     ddl_u) * 16 + b_u];
            float fraw = sRaw[( 8 + ddl_u) * 16 + b_u];
            float zraw = sRaw[(16 + ddl_u) * 16 + b_u];
            float oraw = sRaw[(24 + ddl_u) * 16 + b_u];
            float lf   = st_m + logsigf(fraw);
            float mnew = (t == 0) ? iraw : fmaxf(iraw, lf);  // all(n==0) only at t=0
            float og   = 1.0f / (1.0f + expf(-oraw));
            float ig   = expf(iraw - mnew);
            float fg   = expf(lf - mnew);
            float cn   = fg * st_c + ig * tanhf(zraw);
            float nn   = fg * st_h + ig;                     // reference uses h here
            float hn   = og * cn / nn;
            st_c = cn; st_n = nn; st_m = mnew; st_h = hn;
            out[(t * BATCH + b_u) * HID + q_u] = hn;
            __stcg(&g_h[buf ^ 1][b_u][q_u], hn);
            __threadfence();
        }
        __syncthreads();

        // Global barrier (all 128 CTAs resident -> deadlock-free)
        if (tid == 0) {
            unsigned int ticket = atomicAdd(&g_bar_count, 1u);
            if (ticket == NCTA - 1) {
                g_bar_count = 0u;
                __threadfence();
                atomicAdd(&g_bar_gen, 1u);
            } else {
                while (*((volatile unsigned int*)&g_bar_gen) < (unsigned)(t + 1)) { }
            }
        }
        __syncthreads();
    }

    if (tid < 128) {
        const int FS = T_STEPS * BATCH * HID;
        out[FS + 0 * BATCH * HID + b_u * HID + q_u] = st_h;
        out[FS + 1 * BATCH * HID + b_u * HID + q_u] = st_c;
        out[FS + 2 * BATCH * HID + b_u * HID + q_u] = st_n;
        out[FS + 3 * BATCH * HID + b_u * HID + q_u] = st_m;
    }
}

extern "C" void kernel_launch(void* const* d_in, const int* in_sizes, int n_in,
                              void* d_out, int out_size) {
    const float* x    = (const float*)d_in[0];
    const float* rk   = (const float*)d_in[1];
    const float* bias = (const float*)d_in[2];
    float* out        = (float*)d_out;

    const int smem_bytes = (32 * WSTRIDE + 16 * HSTRIDE + 32 * 16) * 4; // ~52KB
    cudaFuncSetAttribute(slstm_kernel,
                         cudaFuncAttributeMaxDynamicSharedMemorySize, smem_bytes);

    prep_kernel<<<32, 256>>>();
    slstm_kernel<<<NCTA, TPB, smem_bytes>>>(x, rk, bias, out);
}

// round 2
// speedup vs baseline: 1.0996x; 1.0996x over previous
#include <cuda_runtime.h>

// sLSTM, T=512 serial steps, B=16, HID=1024, H=4 heads (D=256), G=4 gates.
// Grid 128 persistent (occ 1, guaranteed co-resident). Heads are independent:
// per-head flag-array sync (release/acquire), h_t exchanged through `out` itself.
// GEMM: 8r x 8b warp tiles, f32x2 packed FMA, SMEM-resident weights.

#define T_STEPS 512
#define BATCH   16
#define HID     1024
#define NCTA    128
#define TPB     256
#define WS      260   // 256 + 4 pad -> consecutive rows 4 banks apart
#define HS      260

__device__ unsigned g_flag[128];   // [head*32 + ctaInHead], = steps completed

__global__ void prep_kernel() {
    int i = threadIdx.x;
    if (i < 128) g_flag[i] = 0u;
}

__device__ __forceinline__ void ffma2(unsigned long long &acc,
                                      unsigned long long a,
                                      unsigned long long b) {
    asm("fma.rn.f32x2 %0, %1, %2, %0;" : "+l"(acc) : "l"(a), "l"(b));
}
__device__ __forceinline__ float fold2(unsigned long long a) {
    return __uint_as_float((unsigned)(a & 0xffffffffu)) +
           __uint_as_float((unsigned)(a >> 32));
}
__device__ __forceinline__ float logsigf(float v) {
    float l = log1pf(expf(-fabsf(v)));
    return (v < 0.0f ? v : 0.0f) - l;
}
__device__ __forceinline__ unsigned ld_acq(const unsigned* p) {
    unsigned v;
    asm volatile("ld.acquire.gpu.global.u32 %0, [%1];" : "=r"(v) : "l"(p));
    return v;
}
__device__ __forceinline__ void st_rel(unsigned* p, unsigned v) {
    asm volatile("st.release.gpu.global.u32 [%0], %1;" :: "l"(p), "r"(v) : "memory");
}

__global__ __launch_bounds__(TPB, 1) void slstm_kernel(
    const float* __restrict__ x,     // (512, 16, 4096)
    const float* __restrict__ rk,    // (4, 256, 4, 256)
    const float* __restrict__ bias,  // flat 4096
    float* __restrict__ out)         // outs (512,16,1024) ++ final (4,16,1024)
{
    __shared__ float sW[32 * WS];
    __shared__ float sH[16 * HS];
    __shared__ float sRaw[32 * 16 + 16];

    const int c     = blockIdx.x;
    const int head  = c >> 5;
    const int dd0   = (c & 31) << 3;          // 8 channels per CTA
    const int hbase = head << 8;
    const int tid   = threadIdx.x;
    const int wid   = tid >> 5;
    const int lane  = tid & 31;

    // One-time weight gather: W[r][d] = rk[head, (d%64)*4+g2, dd/64, (dd%64)*4 + d/64]
    for (int idx = tid; idx < 32 * 256; idx += TPB) {
        int r  = idx >> 8, d = idx & 255;
        int g2 = r >> 3;
        int dd = dd0 + (r & 7);
        int a  = ((d & 63) << 2) + g2;
        int gx = dd >> 6;
        int bb = ((dd & 63) << 2) + (d >> 6);
        sW[r * WS + d] = rk[((hbase + a) * 4 + gx) * 256 + bb];
    }

    // GEMM role: warp tile 8r x 8b; lane -> (ri, bi) with 2 outputs (bi, bi+4)
    const int rT  = (wid >> 1) << 3;          // 0,8,16,24
    const int bT  = (wid & 1) << 3;           // 0,8
    const int ri  = rT + (lane >> 2);         // row in [0,32)
    const int bi0 = bT + (lane & 3);
    const int bi1 = bi0 + 4;
    const int g2r = ri >> 3;
    const int pr  = (g2r << 10) + hbase + dd0 + (ri & 7);   // channel in [0,4096)
    const float biasv = bias[pr];

    // Elementwise role: tid<128 owns state (channel dl_u, batch b_u)
    const int dl_u = tid >> 4;                // 0..7
    const int b_u  = tid & 15;
    const int q_u  = hbase + dd0 + dl_u;
    float st_h = 0.f, st_c = 0.f, st_n = 0.f, st_m = 0.f;

    // h_{-1} = 0
    for (int i = tid; i < 16 * HS; i += TPB) sH[i] = 0.f;
    __syncthreads();

    for (int t = 0; t < T_STEPS; ++t) {
        // x prefetch (independent of h) — issue before the poll
        float xv0 = __ldg(&x[(t * BATCH + bi0) * 4096 + pr]);
        float xv1 = __ldg(&x[(t * BATCH + bi1) * 4096 + pr]);

        if (t > 0) {
            // Wait until all 32 producer CTAs of this head finished step t-1
            if (wid == 0) {
                const unsigned* fl = &g_flag[head * 32];
                const unsigned tgt = (unsigned)t;
                for (;;) {
                    unsigned f = ld_acq(&fl[lane]);
                    if (__all_sync(0xffffffffu, f >= tgt)) break;
                }
            }
            __syncthreads();
            // Stage h_{t-1} for this head from out: 16 rows x 256 f32 = 1024 float4
            const float* hsrc = out + (size_t)(t - 1) * (BATCH * HID) + hbase;
            #pragma unroll
            for (int kq = 0; kq < 4; ++kq) {
                int i  = tid + kq * TPB;
                int b  = i >> 6;
                int c4 = (i & 63) << 2;
                float4 v = __ldcg((const float4*)(hsrc + b * HID + c4));
                *(float4*)&sH[b * HS + c4] = v;
            }
            __syncthreads();
        }

        // GEMM: out[ri][bi0], out[ri][bi1] over k=256 (64 float4 chunks)
        {
            const char* wp  = (const char*)(sW + ri * WS);
            const char* h0p = (const char*)(sH + bi0 * HS);
            const char* h1p = (const char*)(sH + bi1 * HS);
            unsigned long long a0l = 0ull, a0h = 0ull, a1l = 0ull, a1h = 0ull;
            #pragma unroll 8
            for (int j = 0; j < 64; ++j) {
                ulonglong2 wv = *(const ulonglong2*)(wp  + (j << 4));
                ulonglong2 h0 = *(const ulonglong2*)(h0p + (j << 4));
                ulonglong2 h1 = *(const ulonglong2*)(h1p + (j << 4));
                ffma2(a0l, wv.x, h0.x);
                ffma2(a1l, wv.x, h1.x);
                ffma2(a0h, wv.y, h0.y);
                ffma2(a1h, wv.y, h1.y);
            }
            sRaw[ri * 16 + bi0] = fold2(a0l) + fold2(a0h) + xv0 + biasv;
            sRaw[ri * 16 + bi1] = fold2(a1l) + fold2(a1h) + xv1 + biasv;
        }
        __syncthreads();

        // Elementwise state update (128 threads), h_t written straight into out
        if (tid < 128) {
            float iraw = sRaw[(     dl_u) * 16 + b_u];
            float fraw = sRaw[( 8 + dl_u) * 16 + b_u];
            float zraw = sRaw[(16 + dl_u) * 16 + b_u];
            float oraw = sRaw[(24 + dl_u) * 16 + b_u];
            float lf   = st_m + logsigf(fraw);
            float mnew = (t == 0) ? iraw : fmaxf(iraw, lf);   // all(n==0) only at t=0
            float og   = 1.0f / (1.0f + expf(-oraw));
            float ig   = expf(iraw - mnew);
            float fg   = expf(lf - mnew);
            float cn   = fg * st_c + ig * tanhf(zraw);
            float nn   = fg * st_h + ig;                      // reference uses h here
            float hn   = og * cn / nn;
            st_c = cn; st_n = nn; st_m = mnew; st_h = hn;
            __stcg(&out[(size_t)(t * BATCH + b_u) * HID + q_u], hn);
            __threadfence();   // make h_t L2-visible before this CTA's flag release
        }
        __syncthreads();
        if (tid == 0) st_rel(&g_flag[c], (unsigned)(t + 1));
        // no trailing sync needed: next-step sRaw writes are fenced by the
        // poll/h-load __syncthreads, and flags are monotonic
    }

    if (tid < 128) {
        const size_t FS = (size_t)T_STEPS * BATCH * HID;
        const size_t o  = (size_t)b_u * HID + q_u;
        out[FS + 0 * BATCH * HID + o] = st_h;
        out[FS + 1 * BATCH * HID + o] = st_c;
        out[FS + 2 * BATCH * HID + o] = st_n;
        out[FS + 3 * BATCH * HID + o] = st_m;
    }
}

extern "C" void kernel_launch(void* const* d_in, const int* in_sizes, int n_in,
                              void* d_out, int out_size) {
    const float* x    = (const float*)d_in[0];
    const float* rk   = (const float*)d_in[1];
    const float* bias = (const float*)d_in[2];
    float* out        = (float*)d_out;

    prep_kernel<<<1, 128>>>();
    slstm_kernel<<<NCTA, TPB>>>(x, rk, bias, out);
}

// round 7
// speedup vs baseline: 2.0638x; 1.8769x over previous
#include <cuda_runtime.h>

// sLSTM, T=512 serial steps, B=16, HID=1024, H=4 heads (D=256), G=4 gates.
// 128 persistent CTAs (32 per head, 8 channels each). Per-head flag sync.
// GEMM: W in REGISTERS (128/thread, step-invariant), thread tile 4r x 4b x 32k,
// shfl k-reduction, XOR-swizzled h tile in smem, f32x2 packed FMA.
// R4 fix: W indexed at LOGICAL j (h slot j^swc holds logical element j);
// also keeps W indices compile-time -> W stays in registers.

#define T_STEPS 512
#define BATCH   16
#define HID     1024
#define NCTA    128
#define TPB     256
#define RS      17     // sRaw row stride (words)

__device__ unsigned g_flag[NCTA];   // [head*32 + ctaInHead] = steps completed

__global__ void prep_kernel() {
    int i = threadIdx.x;
    if (i < NCTA) g_flag[i] = 0u;
}

__device__ __forceinline__ void ffma2(unsigned long long &acc,
                                      unsigned long long a,
                                      unsigned long long b) {
    asm("fma.rn.f32x2 %0, %1, %2, %0;" : "+l"(acc) : "l"(a), "l"(b));
}
__device__ __forceinline__ float fold2(unsigned long long a) {
    return __uint_as_float((unsigned)(a & 0xffffffffu)) +
           __uint_as_float((unsigned)(a >> 32));
}
__device__ __forceinline__ float logsigf(float v) {
    float l = log1pf(expf(-fabsf(v)));
    return (v < 0.0f ? v : 0.0f) - l;
}
__device__ __forceinline__ unsigned ld_acq(const unsigned* p) {
    unsigned v;
    asm volatile("ld.acquire.gpu.global.u32 %0, [%1];" : "=r"(v) : "l"(p));
    return v;
}
__device__ __forceinline__ void st_rel(unsigned* p, unsigned v) {
    asm volatile("st.release.gpu.global.u32 [%0], %1;" :: "l"(p), "r"(v) : "memory");
}

__global__ __launch_bounds__(TPB, 1) void slstm_kernel(
    const float* __restrict__ x,     // (512, 16, 4096)
    const float* __restrict__ rk,    // (4, 256, 4, 256)
    const float* __restrict__ bias,  // flat 4096
    float* __restrict__ out)         // outs (512,16,1024) ++ final (4,16,1024)
{
    // h tile: 16 batch rows x 64 float4 (k=256), stride 65 f4, XOR-swizzled
    __shared__ float4 sH4[16 * 65];
    __shared__ float  sRaw[32 * RS];

    const int c     = blockIdx.x;
    const int head  = c >> 5;
    const int dd0   = (c & 31) << 3;   // 8 channels of this CTA
    const int hbase = head << 8;
    const int tid   = threadIdx.x;
    const int wq    = tid >> 5;        // warp = row-tile (rows 4wq..4wq+3)
    const int lane  = tid & 31;
    const int btile = lane & 3;        // batches 4*btile..+3
    const int ks    = lane >> 2;       // k-slice 32*ks..+31
    const int swc   = (ks ^ (btile << 1)) & 7;   // h slot swizzle constant

    // ---- one-time W gather into registers ----
    // W[row][d] = rk[head, (d%64)*4+g2, dd/64, (dd%64)*4 + d/64],
    // row = 8*g2 + local_chan; this thread: rows 4wq+i, d = 32*ks + 4j + e
    float Wf[128];   // [(i*8+j)*4 + e]
    #pragma unroll
    for (int i = 0; i < 4; ++i) {
        int row = 4 * wq + i;
        int g2  = row >> 3;
        int dd  = dd0 + (row & 7);
        int gx  = dd >> 6;
        int bbs = (dd & 63) << 2;
        #pragma unroll
        for (int j = 0; j < 8; ++j) {
            #pragma unroll
            for (int e = 0; e < 4; ++e) {
                int d  = 32 * ks + 4 * j + e;
                int a  = ((d & 63) << 2) + g2;
                int bb = bbs + (d >> 6);
                Wf[(i * 8 + j) * 4 + e] = __ldg(&rk[((hbase + a) * 4 + gx) * 256 + bb]);
            }
        }
    }
    const unsigned long long* W2 = (const unsigned long long*)Wf;  // [(i*8+j)*2 + {0,1}]

    // ---- elementwise role: tid<128 owns (channel dl_u, batch b_u) ----
    const int dl_u = tid >> 4;         // 0..7
    const int b_u  = tid & 15;
    const int q_u  = hbase + dd0 + dl_u;
    float bias_g[4];
    #pragma unroll
    for (int g = 0; g < 4; ++g)
        bias_g[g] = bias[(g << 10) + hbase + dd0 + dl_u];
    float st_h = 0.f, st_c = 0.f, st_n = 0.f, st_m = 0.f;

    // h_{-1} = 0
    {
        float4 z = make_float4(0.f, 0.f, 0.f, 0.f);
        for (int i = tid; i < 16 * 65; i += TPB) sH4[i] = z;
    }
    __syncthreads();

    const unsigned long long* sH2 = (const unsigned long long*)sH4;

    for (int t = 0; t < T_STEPS; ++t) {
        // x prefetch for elementwise (independent of h) — before the poll
        float xr0 = 0.f, xr1 = 0.f, xr2 = 0.f, xr3 = 0.f;
        if (tid < 128) {
            const float* xb = x + (size_t)(t * BATCH + b_u) * 4096 + hbase + dd0 + dl_u;
            xr0 = __ldg(xb);
            xr1 = __ldg(xb + 1024);
            xr2 = __ldg(xb + 2048);
            xr3 = __ldg(xb + 3072);
        }

        if (t > 0) {
            if (wq == 0) {   // warp 0 polls the 32 producer flags of this head
                const unsigned* fl = &g_flag[head * 32];
                const unsigned tgt = (unsigned)t;
                for (;;) {
                    unsigned f = ld_acq(&fl[lane]);
                    if (__all_sync(0xffffffffu, f >= tgt)) break;
                }
            }
            __syncthreads();
            // stage h_{t-1}[head slice]: 16 x 64 float4, swizzled store
            const float4* hsrc = (const float4*)(out + (size_t)(t - 1) * (BATCH * HID) + hbase);
            #pragma unroll
            for (int kq = 0; kq < 4; ++kq) {
                int i = tid + kq * TPB;
                int b = i >> 6;
                int f = i & 63;
                int s = f ^ (((f >> 3) ^ ((b >> 2) << 1)) & 7);
                sH4[b * 65 + s] = __ldcg(hsrc + (b << 8) + f);
            }
            __syncthreads();
        }

        // ---- GEMM: rows 4wq..+3 x batches 4btile..+3, k-slice 32*ks..+31 ----
        unsigned long long acc[16];
        #pragma unroll
        for (int q = 0; q < 16; ++q) acc[q] = 0ull;

        #pragma unroll
        for (int j = 0; j < 8; ++j) {
            // h slot (j ^ swc) holds LOGICAL element j of the k-slice
            unsigned long long hlo[4], hhi[4];
            #pragma unroll
            for (int bi = 0; bi < 4; ++bi) {
                int b   = 4 * btile + bi;
                int idx = (b * 65 + 8 * ks + (j ^ swc)) * 2;
                hlo[bi] = sH2[idx];
                hhi[bi] = sH2[idx + 1];
            }
            #pragma unroll
            for (int i = 0; i < 4; ++i) {
                // W for LOGICAL element j (compile-time index -> stays in regs)
                unsigned long long wlo = W2[(i * 8 + j) * 2];
                unsigned long long whi = W2[(i * 8 + j) * 2 + 1];
                #pragma unroll
                for (int bi = 0; bi < 4; ++bi) {
                    ffma2(acc[i * 4 + bi], wlo, hlo[bi]);
                    ffma2(acc[i * 4 + bi], whi, hhi[bi]);
                }
            }
        }

        // k-slice reduction across lanes (xor 4, 8, 16), then lanes 0..3 write
        float red[16];
        #pragma unroll
        for (int q = 0; q < 16; ++q) {
            float v = fold2(acc[q]);
            v += __shfl_xor_sync(0xffffffffu, v, 4);
            v += __shfl_xor_sync(0xffffffffu, v, 8);
            v += __shfl_xor_sync(0xffffffffu, v, 16);
            red[q] = v;
        }
        if (ks == 0) {
            #pragma unroll
            for (int i = 0; i < 4; ++i)
                #pragma unroll
                for (int bi = 0; bi < 4; ++bi)
                    sRaw[(4 * wq + i) * RS + 4 * btile + bi] = red[i * 4 + bi];
        }
        __syncthreads();

        // ---- elementwise state update; h_t goes straight into out ----
        if (tid < 128) {
            float iraw = sRaw[(     dl_u) * RS + b_u] + xr0 + bias_g[0];
            float fraw = sRaw[( 8 + dl_u) * RS + b_u] + xr1 + bias_g[1];
            float zraw = sRaw[(16 + dl_u) * RS + b_u] + xr2 + bias_g[2];
            float oraw = sRaw[(24 + dl_u) * RS + b_u] + xr3 + bias_g[3];
            float lf   = st_m + logsigf(fraw);
            float mnew = (t == 0) ? iraw : fmaxf(iraw, lf);   // all(n==0) only at t=0
            float og   = 1.0f / (1.0f + expf(-oraw));
            float ig   = expf(iraw - mnew);
            float fg   = expf(lf - mnew);
            float cn   = fg * st_c + ig * tanhf(zraw);
            float nn   = fg * st_h + ig;                      // reference uses h here
            float hn   = og * cn / nn;
            st_c = cn; st_n = nn; st_m = mnew; st_h = hn;
            __stcg(&out[(size_t)(t * BATCH + b_u) * HID + q_u], hn);
        }
        __syncthreads();
        // transitive happens-before: stores -> barrier -> tid0 release
        if (tid == 0) st_rel(&g_flag[c], (unsigned)(t + 1));
    }

    if (tid < 128) {
        const size_t FS = (size_t)T_STEPS * BATCH * HID;
        const size_t o  = (size_t)b_u * HID + q_u;
        out[FS + 0 * BATCH * HID + o] = st_h;
        out[FS + 1 * BATCH * HID + o] = st_c;
        out[FS + 2 * BATCH * HID + o] = st_n;
        out[FS + 3 * BATCH * HID + o] = st_m;
    }
}

extern "C" void kernel_launch(void* const* d_in, const int* in_sizes, int n_in,
                              void* d_out, int out_size) {
    const float* x    = (const float*)d_in[0];
    const float* rk   = (const float*)d_in[1];
    const float* bias = (const float*)d_in[2];
    float* out        = (float*)d_out;

    prep_kernel<<<1, NCTA>>>();
    slstm_kernel<<<NCTA, TPB>>>(x, rk, bias, out);
}